// round 13
// baseline (speedup 1.0000x reference)
#include <cuda_runtime.h>

// HistogramLayer inference: bias[b] = prod_d hist_probs[bin(b,d), d]
//
// Split-lane layout: lane l = 4g+q owns float4-chunk q. Per iteration the
// warp processes a 64-row tile (8 coalesced LDG.128); a register
// double-buffer prefetches the NEXT tile's 8 loads before the current
// tile's compute, keeping ~8 LDG.128 in flight per warp continuously
// (the R11 version let ptxas collapse the burst; this pins it).
//
// Binning (bit-exact vs searchsorted_right): base=linspace(-4,4,9) is exact
// integers so edges[5][d]==scale_d bit-exactly. Let
//   z  = saturate(fma(x, (1/s)/8, (4 - 1e-4)/8))      (SAT folds into FFMA)
//   t4 = floor(z * 31.996) & ~3                        (= 4 * bin candidate)
// Downward shift of the implied y = x/s + 4 is <= 1e-4 (guard) + 1e-3
// (31.996-vs-32 scale) + 2e-6 (fp rounding) < 1 bin and never negative,
// so b_true in {t, t+1}; resolved EXACTLY by the stored-edge test
// b = t + (x >= e_{t+1}) (+inf sentinel at t=7 so the +1 never crosses a
// feature boundary; clamped ends are fixup-free). ONE probability LDS per
// element: pb = s_pt[idx + (x >= hi)].
//
// Shared tables are stride-1 fp32, byte-indexed tb4 + t4 with
// tb4 = i*128 + q*32: within any warp step the 32 lanes cover 32 distinct
// banks (duplicates broadcast) -> conflict-free LDS.32.

#define D    16
#define NB   8
#define TPB  256
#define RPT  4
#define ROWS_PER_WARP  (RPT * 64)                      // 256
#define ROWS_PER_BLOCK ((TPB / 32) * ROWS_PER_WARP)    // 2048

__global__ __launch_bounds__(TPB)
void hist_kernel(const float4* __restrict__ inp4,
                 const float* __restrict__ freq,
                 const float* __restrict__ edges,
                 float* __restrict__ out, int nrows)
{
    __shared__ float s_hi[4 * 32];        // [i][8q+t] = e_{t+1} (+inf at t=7)
    __shared__ float s_pt[4 * 32 + 1];    // [i][8q+t] = p_t (+1 pad, never read)
    __shared__ float s_a [D];             // (1/scale_d) / 8
    __shared__ float s_e [(NB + 1) * D];  // raw edges staging [j][d]

    const int tid = threadIdx.x;
    if (tid < (NB + 1) * D) s_e[tid] = edges[tid];
    __syncthreads();

    if (tid < D) {
        const int d = tid;
        const int slot = (d & 3) * 32 + (d >> 2) * 8;   // i*32 + q*8
        float ssum = 0.f;
        #pragma unroll
        for (int b = 0; b < NB; ++b) ssum += freq[b * D + d];
        const float inv  = 1.0f / ssum;
        const float pinf = __int_as_float(0x7f800000);
        #pragma unroll
        for (int t = 0; t < NB; ++t) {
            s_pt[slot + t] = freq[t * D + d] * inv;
            s_hi[slot + t] = (t == NB - 1) ? pinf : s_e[(t + 1) * D + d];
        }
        // edges[5][d] == scale_d bit-exactly; /8 is an exact exponent shift
        s_a[d] = (1.0f / s_e[5 * D + d]) * 0.125f;
    }
    if (tid == 0) s_pt[4 * 32] = 0.f;
    __syncthreads();

    const int lane = tid & 31;
    const int q    = lane & 3;
    const int g    = lane >> 2;
    const int warp = tid >> 5;
    const int qb4  = q * 32;              // byte offset of this lane's q-block

    float av[4];
    #pragma unroll
    for (int i = 0; i < 4; ++i) av[i] = s_a[4 * q + i];

    const int wbase = blockIdx.x * ROWS_PER_BLOCK + warp * ROWS_PER_WARP;
    const float4* p4 = inp4 + (unsigned)wbase * 4 + lane;  // coalesced base

    const char* chi = (const char*)s_hi;
    const char* cpt = (const char*)s_pt;

    if (wbase + ROWS_PER_WARP <= nrows) {
        // ---------- full tile: branch-free, software-pipelined ----------
        float4 cur[8];
        #pragma unroll
        for (int k = 0; k < 8; ++k) cur[k] = __ldcs(&p4[k * 32]);

        #pragma unroll 2
        for (int it = 0; it < RPT; ++it) {
            // prefetch next tile (last iter re-reads tile 0: in-bounds, unused)
            const int nofs = (it == RPT - 1) ? 0 : (it + 1) * 256;
            float4 nxt[8];
            #pragma unroll
            for (int k = 0; k < 8; ++k) nxt[k] = __ldcs(&p4[nofs + k * 32]);

            float pr[8] = {1.f, 1.f, 1.f, 1.f, 1.f, 1.f, 1.f, 1.f};
            #pragma unroll
            for (int i = 0; i < 4; ++i) {
                const int tb4 = i * 128 + qb4;
                #pragma unroll
                for (int k = 0; k < 8; ++k) {
                    const float x = (i == 0) ? cur[k].x : (i == 1) ? cur[k].y
                                  : (i == 2) ? cur[k].z : cur[k].w;
                    const float z = __saturatef(fmaf(x, av[i], 0.49998750f));
                    const int t4 = __float2int_rd(z * 31.996f) & ~3;
                    const float hi = *(const float*)(chi + tb4 + t4);
                    const int s4 = (x >= hi) ? 4 : 0;
                    pr[k] *= *(const float*)(cpt + tb4 + t4 + s4);
                }
            }
            #pragma unroll
            for (int k = 0; k < 8; ++k) {
                pr[k] *= __shfl_xor_sync(0xffffffffu, pr[k], 1);
                pr[k] *= __shfl_xor_sync(0xffffffffu, pr[k], 2);
            }
            if (q == 0) {
                const int r0 = wbase + it * 64 + g;
                #pragma unroll
                for (int k = 0; k < 8; ++k) __stcs(&out[r0 + 8 * k], pr[k]);
            }
            #pragma unroll
            for (int k = 0; k < 8; ++k) cur[k] = nxt[k];
        }
    } else {
        // ---------- tail tile: guarded (never taken when B % 2048 == 0) ---
        #pragma unroll 1
        for (int it = 0; it < RPT; ++it) {
            float4 v[8];
            #pragma unroll
            for (int k = 0; k < 8; ++k) {
                const int row = wbase + it * 64 + 8 * k + g;
                v[k] = (row < nrows) ? p4[it * 256 + k * 32]
                                     : make_float4(0.f, 0.f, 0.f, 0.f);
            }
            float pr[8] = {1.f, 1.f, 1.f, 1.f, 1.f, 1.f, 1.f, 1.f};
            #pragma unroll
            for (int i = 0; i < 4; ++i) {
                const int tb4 = i * 128 + qb4;
                #pragma unroll
                for (int k = 0; k < 8; ++k) {
                    const float x = (i == 0) ? v[k].x : (i == 1) ? v[k].y
                                  : (i == 2) ? v[k].z : v[k].w;
                    const float z = __saturatef(fmaf(x, av[i], 0.49998750f));
                    const int t4 = __float2int_rd(z * 31.996f) & ~3;
                    const float hi = *(const float*)(chi + tb4 + t4);
                    const int s4 = (x >= hi) ? 4 : 0;
                    pr[k] *= *(const float*)(cpt + tb4 + t4 + s4);
                }
            }
            #pragma unroll
            for (int k = 0; k < 8; ++k) {
                pr[k] *= __shfl_xor_sync(0xffffffffu, pr[k], 1);
                pr[k] *= __shfl_xor_sync(0xffffffffu, pr[k], 2);
            }
            if (q == 0) {
                const int r0 = wbase + it * 64 + g;
                #pragma unroll
                for (int k = 0; k < 8; ++k)
                    if (r0 + 8 * k < nrows) out[r0 + 8 * k] = pr[k];
            }
        }
    }
}

extern "C" void kernel_launch(void* const* d_in, const int* in_sizes, int n_in,
                              void* d_out, int out_size)
{
    const float4* inp4 = (const float4*)d_in[0];  // [B,16] fp32 = float4[B*4]
    const float*  freq = (const float*)d_in[1];   // [8,16] fp32
    const float*  edges= (const float*)d_in[2];   // [9,16] fp32
    float* out = (float*)d_out;                   // [B] fp32

    const int nrows = out_size;
    const int grid = (nrows + ROWS_PER_BLOCK - 1) / ROWS_PER_BLOCK;
    hist_kernel<<<grid, TPB>>>(inp4, freq, edges, out, nrows);
}